// round 1
// baseline (speedup 1.0000x reference)
#include <cuda_runtime.h>
#include <cuda_bf16.h>

// ---------------------------------------------------------------------------
// TGNN baseline: layer-wise fp32 SGEMM pipeline.
//
// Network:
//   h384 = [relu(p[:, :64]@aw+ab), relu(p[:,64:128]@aw+ab), relu(p[:,128:]@bw+bb)]
//   h512 = relu(h384 @ p1w + p1b)
//   h256 = relu(h512 @ p2w + p2b)
//   hm   = segment_mean(h256, group=100)           // reduce BEFORE p3 (linear)
//   y    = hm @ p3w + p3b                          // only 2000 rows now
//   z    = relu(y @ f1w + f1b)
//   w    = relu(z @ f2w + f2b)
//   out  = w @ f3w + f3b
// ---------------------------------------------------------------------------

#define P_MAX  200000
#define B_MAX  2000

// __device__ global scratch (allocation-free requirement)
__device__ float g_h384[(size_t)P_MAX * 384];
__device__ float g_h512[(size_t)P_MAX * 512];
__device__ float g_h256[(size_t)P_MAX * 256];
__device__ float g_hm  [(size_t)B_MAX * 256];
__device__ float g_y   [(size_t)B_MAX * 1024];
__device__ float g_z   [(size_t)B_MAX * 512];
__device__ float g_w   [(size_t)B_MAX * 32];

// ---------------------------------------------------------------------------
// Generic SGEMM: C[M,N] = act(A[M,K] @ W[K,N] + bias), all row-major.
// BM=128, BN=128, BK=8, 256 threads, 8x8 per-thread microtile.
// Requirements: K % 8 == 0, N % 4 == 0, A rows 16B-aligned at (row*lda + k0).
// ---------------------------------------------------------------------------
#define BM 128
#define BN 128
#define BK 8
#define TM 8
#define TN 8

__global__ __launch_bounds__(256, 2)
void gemm_bias_act(const float* __restrict__ A, int lda,
                   const float* __restrict__ W, int ldw,
                   const float* __restrict__ bias,
                   float* __restrict__ C, int ldc,
                   int M, int N, int K, int relu)
{
    __shared__ __align__(16) float As[BK][BM];
    __shared__ __align__(16) float Ws[BK][BN];

    const int tid = threadIdx.x;
    const int blockRow = blockIdx.y * BM;
    const int blockCol = blockIdx.x * BN;

    // A tile loader: 128 rows x 8 cols, each thread loads one float4
    const int arow = tid >> 1;          // 0..127
    const int acol = (tid & 1) * 4;     // 0 or 4
    // W tile loader: 8 rows x 128 cols, each thread loads one float4
    const int wrow = tid >> 5;          // 0..7
    const int wcol = (tid & 31) * 4;    // 0..124

    const int tm = (tid >> 4) * TM;     // 0..120
    const int tn = (tid & 15) * TN;     // 0..120

    float acc[TM][TN];
#pragma unroll
    for (int i = 0; i < TM; i++)
#pragma unroll
        for (int j = 0; j < TN; j++) acc[i][j] = 0.0f;

    for (int k0 = 0; k0 < K; k0 += BK) {
        // --- load A tile (guard rows) ---
        {
            const int gr = blockRow + arow;
            float4 v = make_float4(0.f, 0.f, 0.f, 0.f);
            if (gr < M)
                v = *reinterpret_cast<const float4*>(A + (size_t)gr * lda + k0 + acol);
            As[acol + 0][arow] = v.x;
            As[acol + 1][arow] = v.y;
            As[acol + 2][arow] = v.z;
            As[acol + 3][arow] = v.w;
        }
        // --- load W tile (guard cols) ---
        {
            const int gk = k0 + wrow;
            const int gn = blockCol + wcol;
            float4 v = make_float4(0.f, 0.f, 0.f, 0.f);
            if (gn < N)
                v = *reinterpret_cast<const float4*>(W + (size_t)gk * ldw + gn);
            Ws[wrow][wcol + 0] = v.x;
            Ws[wrow][wcol + 1] = v.y;
            Ws[wrow][wcol + 2] = v.z;
            Ws[wrow][wcol + 3] = v.w;
        }
        __syncthreads();

#pragma unroll
        for (int k = 0; k < BK; k++) {
            float ra[TM], rb[TN];
            // vectorized smem reads (16B)
            *reinterpret_cast<float4*>(&ra[0]) = *reinterpret_cast<const float4*>(&As[k][tm]);
            *reinterpret_cast<float4*>(&ra[4]) = *reinterpret_cast<const float4*>(&As[k][tm + 4]);
            *reinterpret_cast<float4*>(&rb[0]) = *reinterpret_cast<const float4*>(&Ws[k][tn]);
            *reinterpret_cast<float4*>(&rb[4]) = *reinterpret_cast<const float4*>(&Ws[k][tn + 4]);
#pragma unroll
            for (int i = 0; i < TM; i++)
#pragma unroll
                for (int j = 0; j < TN; j++)
                    acc[i][j] = fmaf(ra[i], rb[j], acc[i][j]);
        }
        __syncthreads();
    }

    // --- epilogue: bias + optional relu ---
#pragma unroll
    for (int i = 0; i < TM; i++) {
        const int gm = blockRow + tm + i;
        if (gm >= M) continue;
#pragma unroll
        for (int j = 0; j < TN; j++) {
            const int gn = blockCol + tn + j;
            if (gn >= N) continue;
            float v = acc[i][j] + bias[gn];
            if (relu) v = fmaxf(v, 0.0f);
            C[(size_t)gm * ldc + gn] = v;
        }
    }
}

// ---------------------------------------------------------------------------
// Segment mean: one block per group; 256 threads = 256 columns.
// ---------------------------------------------------------------------------
__global__ void seg_mean_kernel(const float* __restrict__ h,
                                const int* __restrict__ idx,
                                float* __restrict__ hm,
                                int group)
{
    const int b = blockIdx.x;
    const int c = threadIdx.x;              // 0..255
    const float* base = h + (size_t)b * group * 256 + c;
    float s = 0.0f;
    for (int i = 0; i < group; i++) s += base[(size_t)i * 256];
    hm[(size_t)b * 256 + c] = s / (float)idx[b];
}

// ---------------------------------------------------------------------------
// Final: out[r] = dot(w[r, :32], f3w) + f3b
// ---------------------------------------------------------------------------
__global__ void final_kernel(const float* __restrict__ w,
                             const float* __restrict__ f3w,
                             const float* __restrict__ f3b,
                             float* __restrict__ out, int B)
{
    const int r = blockIdx.x * blockDim.x + threadIdx.x;
    if (r >= B) return;
    float s = 0.0f;
#pragma unroll
    for (int k = 0; k < 32; k++) s = fmaf(w[(size_t)r * 32 + k], f3w[k], s);
    out[r] = s + f3b[0];
}

// ---------------------------------------------------------------------------

static inline dim3 gemm_grid(int M, int N) {
    return dim3((N + BN - 1) / BN, (M + BM - 1) / BM);
}

extern "C" void kernel_launch(void* const* d_in, const int* in_sizes, int n_in,
                              void* d_out, int out_size)
{
    const float* pairs     = (const float*)d_in[0];   // [P,160]
    const int*   idx_pairs = (const int*)  d_in[1];   // [B]
    // d_in[2] = ref_feats (unused by reference)
    const float* aw  = (const float*)d_in[3];
    const float* ab  = (const float*)d_in[4];
    const float* bw  = (const float*)d_in[5];
    const float* bb  = (const float*)d_in[6];
    const float* p1w = (const float*)d_in[7];
    const float* p1b = (const float*)d_in[8];
    const float* p2w = (const float*)d_in[9];
    const float* p2b = (const float*)d_in[10];
    const float* p3w = (const float*)d_in[11];
    const float* p3b = (const float*)d_in[12];
    const float* f1w = (const float*)d_in[13];
    const float* f1b = (const float*)d_in[14];
    const float* f2w = (const float*)d_in[15];
    const float* f2b = (const float*)d_in[16];
    const float* f3w = (const float*)d_in[17];
    const float* f3b = (const float*)d_in[18];
    float* out = (float*)d_out;

    const int P = in_sizes[0] / 160;
    const int B = in_sizes[1];
    const int group = P / B;                          // 100

    float *h384, *h512, *h256, *hm, *y, *z, *w;
    cudaGetSymbolAddress((void**)&h384, g_h384);
    cudaGetSymbolAddress((void**)&h512, g_h512);
    cudaGetSymbolAddress((void**)&h256, g_h256);
    cudaGetSymbolAddress((void**)&hm,   g_hm);
    cudaGetSymbolAddress((void**)&y,    g_y);
    cudaGetSymbolAddress((void**)&z,    g_z);
    cudaGetSymbolAddress((void**)&w,    g_w);

    // ---- embed layers into h384 (3 column slabs) ----
    gemm_bias_act<<<gemm_grid(P, 128), 256>>>(pairs,        160, aw, 128, ab, h384,       384, P, 128, 64, 1);
    gemm_bias_act<<<gemm_grid(P, 128), 256>>>(pairs + 64,   160, aw, 128, ab, h384 + 128, 384, P, 128, 64, 1);
    gemm_bias_act<<<gemm_grid(P, 128), 256>>>(pairs + 128,  160, bw, 128, bb, h384 + 256, 384, P, 128, 32, 1);

    // ---- trunk ----
    gemm_bias_act<<<gemm_grid(P, 512), 256>>>(h384, 384, p1w, 512, p1b, h512, 512, P, 512, 384, 1);
    gemm_bias_act<<<gemm_grid(P, 256), 256>>>(h512, 512, p2w, 256, p2b, h256, 256, P, 256, 512, 1);

    // ---- segment mean BEFORE p3 (p3 is linear; mean commutes) ----
    seg_mean_kernel<<<B, 256>>>(h256, idx_pairs, hm, group);

    // ---- batch-level layers (M = 2000) ----
    gemm_bias_act<<<gemm_grid(B, 1024), 256>>>(hm, 256, p3w, 1024, p3b, y, 1024, B, 1024, 256, 0);
    gemm_bias_act<<<gemm_grid(B, 512),  256>>>(y, 1024, f1w, 512,  f1b, z, 512,  B, 512, 1024, 1);
    gemm_bias_act<<<gemm_grid(B, 32),   256>>>(z, 512,  f2w, 32,   f2b, w, 32,   B, 32,  512,  1);

    final_kernel<<<(B + 255) / 256, 256>>>(w, f3w, f3b, out, B);
}

// round 3
// speedup vs baseline: 2.8551x; 2.8551x over previous
#include <cuda_runtime.h>
#include <cuda_bf16.h>
#include <cstdint>

// ===========================================================================
// TGNN — mma.sync tf32 GEMM pipeline (legacy tensor path; tcgen05 is not
// available because the harness compiles at virtual target compute_103).
//
//   h384 = [relu(p[:,:64]@aw+ab), relu(p[:,64:128]@aw+ab), relu(p[:,128:]@bw+bb)]
//   h512 = relu(h384 @ p1w + p1b)
//   h256 = relu(h512 @ p2w + p2b)
//   hm   = segment_mean(h256)          // mean BEFORE p3 (p3 linear)
//   p3/f1/f2/f3: fp32 SIMT on B=2000 rows
// ===========================================================================

#define P_MAX  200000
#define B_MAX  2000

__device__ float g_h384[(size_t)P_MAX * 384];
__device__ float g_h512[(size_t)P_MAX * 512];
__device__ float g_h256[(size_t)P_MAX * 256];
__device__ float g_hm  [(size_t)B_MAX * 256];
__device__ float g_y   [(size_t)B_MAX * 1024];
__device__ float g_z   [(size_t)B_MAX * 512];
__device__ float g_w   [(size_t)B_MAX * 32];
__device__ float g_wt  [512 * 1024];          // rounded weights scratch

__device__ __forceinline__ float tf32_round(float x) {
    uint32_t r;
    asm("cvt.rna.tf32.f32 %0, %1;" : "=r"(r) : "f"(x));
    return __uint_as_float(r);
}
__device__ __forceinline__ uint32_t tf32_round_bits(float x) {
    uint32_t r;
    asm("cvt.rna.tf32.f32 %0, %1;" : "=r"(r) : "f"(x));
    return r;
}

__device__ __forceinline__ void cp_async16(uint32_t smem_addr, const void* gptr, int src_bytes) {
    asm volatile("cp.async.ca.shared.global [%0], [%1], 16, %2;\n"
                 :: "r"(smem_addr), "l"(gptr), "r"(src_bytes));
}
#define CP_ASYNC_COMMIT() asm volatile("cp.async.commit_group;\n" ::: "memory")
#define CP_ASYNC_WAIT0()  asm volatile("cp.async.wait_group 0;\n" ::: "memory")

__device__ __forceinline__ uint32_t smem_u32(const void* p) {
    uint32_t a;
    asm("{ .reg .u64 t; cvta.to.shared.u64 t, %1; cvt.u32.u64 %0, t; }" : "=r"(a) : "l"(p));
    return a;
}

__device__ __forceinline__ void mma_tf32(float& c0, float& c1, float& c2, float& c3,
                                         uint32_t a0, uint32_t a1, uint32_t a2, uint32_t a3,
                                         uint32_t b0, uint32_t b1) {
    asm volatile(
        "mma.sync.aligned.m16n8k8.row.col.f32.tf32.tf32.f32 "
        "{%0,%1,%2,%3}, {%4,%5,%6,%7}, {%8,%9}, {%0,%1,%2,%3};"
        : "+f"(c0), "+f"(c1), "+f"(c2), "+f"(c3)
        : "r"(a0), "r"(a1), "r"(a2), "r"(a3), "r"(b0), "r"(b1));
}

// ---------------------------------------------------------------------------
// Tensor GEMM: C[M,N] = act(A[M,K] @ W[K,N] + bias)
//   BM=128, BN=128, BK=16, 256 threads, double-buffered cp.async.
//   As[m][k]: stride 20 floats (pad 4)  -> conflict-free fragment loads
//   Bs[k][n]: stride 136 floats (pad 8) -> conflict-free fragment loads
//   K % 16 == 0, N % 128 == 0. M guarded.
// ---------------------------------------------------------------------------
#define ASTRIDE 20
#define BSTRIDE 136
#define ASZ (128 * ASTRIDE * 4)          // 10240 B
#define BSZ (16 * BSTRIDE * 4)           // 8704 B
#define STG (ASZ + BSZ)                  // 18944 B
#define SMEM_TOTAL (2 * STG)             // 37888 B < 48K

__global__ __launch_bounds__(256)
void tc_gemm(const float* __restrict__ A, int lda,
             const float* __restrict__ W,        // [K][N], pre-rounded tf32
             const float* __restrict__ bias,
             float* __restrict__ C, int ldc,
             int M, int N, int K,
             int relu, int round_out, int cvt_a)
{
    __shared__ __align__(16) char smem[SMEM_TOTAL];
    const uint32_t smem_base = smem_u32(smem);

    const int tid  = threadIdx.x;
    const int wid  = tid >> 5;
    const int lane = tid & 31;
    const int g    = lane >> 2;          // 0..7
    const int t    = lane & 3;           // 0..3

    const int blockRow = blockIdx.x * 128;
    const int blockCol = blockIdx.y * 128;
    const int warp_m = (wid & 3) * 32;
    const int warp_n = (wid >> 2) * 64;

    // ---- loaders: 2 chunks (16B) each for A and B per tile ----
    // A chunk c: m = c>>2, kc = c&3
    const int am0 = tid >> 2;            // 0..63
    const int akc = tid & 3;
    // B chunk c: k = c>>5, nc = c&31
    const int bk0 = tid >> 5;            // 0..7
    const int bnc = tid & 31;

    const int NIT = K >> 4;

    float acc[2][8][4];
#pragma unroll
    for (int mt = 0; mt < 2; mt++)
#pragma unroll
        for (int nt = 0; nt < 8; nt++)
#pragma unroll
            for (int i = 0; i < 4; i++) acc[mt][nt][i] = 0.0f;

    // ---- tile load helper (as lambda-free macro-style) ----
    auto load_tiles = [&](int it, int stage) {
        const int k0 = it << 4;
        const uint32_t sa = smem_base + stage * STG;
        const uint32_t sb = sa + ASZ;
        // A: rows blockRow+am0 and +64
        {
            int r0 = blockRow + am0;
            int r1 = r0 + 64;
            const char* p0 = (const char*)(A + (size_t)r0 * lda + k0 + akc * 4);
            const char* p1 = (const char*)(A + (size_t)r1 * lda + k0 + akc * 4);
            cp_async16(sa + am0 * (ASTRIDE * 4) + akc * 16, p0, r0 < M ? 16 : 0);
            cp_async16(sa + (am0 + 64) * (ASTRIDE * 4) + akc * 16, p1, r1 < M ? 16 : 0);
        }
        // B: rows k0+bk0 and k0+bk0+8
        {
            const char* p0 = (const char*)(W + (size_t)(k0 + bk0) * N + blockCol + bnc * 4);
            const char* p1 = (const char*)(W + (size_t)(k0 + bk0 + 8) * N + blockCol + bnc * 4);
            cp_async16(sb + bk0 * (BSTRIDE * 4) + bnc * 16, p0, 16);
            cp_async16(sb + (bk0 + 8) * (BSTRIDE * 4) + bnc * 16, p1, 16);
        }
        CP_ASYNC_COMMIT();
    };

    load_tiles(0, 0);
    int fetch = 1;

    for (int it = 0; it < NIT; it++) {
        CP_ASYNC_WAIT0();
        __syncthreads();
        if (fetch < NIT) { load_tiles(fetch, fetch & 1); fetch++; }

        const float* As = (const float*)(smem + (it & 1) * STG);
        const float* Bs = (const float*)(smem + (it & 1) * STG + ASZ);

#pragma unroll
        for (int ks = 0; ks < 2; ks++) {
            uint32_t a[2][4];
#pragma unroll
            for (int mt = 0; mt < 2; mt++) {
                const int m0 = warp_m + mt * 16 + g;
                const int kk = ks * 8 + t;
                a[mt][0] = __float_as_uint(As[m0 * ASTRIDE + kk]);
                a[mt][1] = __float_as_uint(As[(m0 + 8) * ASTRIDE + kk]);
                a[mt][2] = __float_as_uint(As[m0 * ASTRIDE + kk + 4]);
                a[mt][3] = __float_as_uint(As[(m0 + 8) * ASTRIDE + kk + 4]);
            }
            if (cvt_a) {
#pragma unroll
                for (int mt = 0; mt < 2; mt++)
#pragma unroll
                    for (int i = 0; i < 4; i++)
                        a[mt][i] = tf32_round_bits(__uint_as_float(a[mt][i]));
            }
            uint32_t b[8][2];
#pragma unroll
            for (int nt = 0; nt < 8; nt++) {
                const int n0 = warp_n + nt * 8 + g;
                const int kk = ks * 8 + t;
                b[nt][0] = __float_as_uint(Bs[kk * BSTRIDE + n0]);
                b[nt][1] = __float_as_uint(Bs[(kk + 4) * BSTRIDE + n0]);
            }
#pragma unroll
            for (int mt = 0; mt < 2; mt++)
#pragma unroll
                for (int nt = 0; nt < 8; nt++)
                    mma_tf32(acc[mt][nt][0], acc[mt][nt][1], acc[mt][nt][2], acc[mt][nt][3],
                             a[mt][0], a[mt][1], a[mt][2], a[mt][3],
                             b[nt][0], b[nt][1]);
        }
        __syncthreads();
    }

    // ---- epilogue: bias + relu (+tf32 round), float2 stores ----
#pragma unroll
    for (int nt = 0; nt < 8; nt++) {
        const int col = blockCol + warp_n + nt * 8 + 2 * t;
        const float2 bv = *reinterpret_cast<const float2*>(&bias[col]);
#pragma unroll
        for (int mt = 0; mt < 2; mt++) {
#pragma unroll
            for (int half = 0; half < 2; half++) {
                const int row = blockRow + warp_m + mt * 16 + g + half * 8;
                if (row >= M) continue;
                float v0 = acc[mt][nt][half * 2 + 0] + bv.x;
                float v1 = acc[mt][nt][half * 2 + 1] + bv.y;
                if (relu) { v0 = fmaxf(v0, 0.f); v1 = fmaxf(v1, 0.f); }
                if (round_out) { v0 = tf32_round(v0); v1 = tf32_round(v1); }
                *reinterpret_cast<float2*>(C + (size_t)row * ldc + col) = make_float2(v0, v1);
            }
        }
    }
}

// ---------------------------------------------------------------------------
// round_copy: dst[i] = rna_tf32(src[i]), n % 4 == 0
// ---------------------------------------------------------------------------
__global__ void round_copy(const float* __restrict__ src, float* __restrict__ dst, int n4)
{
    int i = blockIdx.x * blockDim.x + threadIdx.x;
    if (i >= n4) return;
    float4 v = reinterpret_cast<const float4*>(src)[i];
    v.x = tf32_round(v.x); v.y = tf32_round(v.y);
    v.z = tf32_round(v.z); v.w = tf32_round(v.w);
    reinterpret_cast<float4*>(dst)[i] = v;
}

// ---------------------------------------------------------------------------
// SIMT fp32 GEMM (proven round-1 kernel) for the small batch-level layers
// ---------------------------------------------------------------------------
#define BM 128
#define BN 128
#define BK 8
#define TM 8
#define TN 8

__global__ __launch_bounds__(256, 2)
void gemm_bias_act(const float* __restrict__ A, int lda,
                   const float* __restrict__ W, int ldw,
                   const float* __restrict__ bias,
                   float* __restrict__ C, int ldc,
                   int M, int N, int K, int relu)
{
    __shared__ __align__(16) float As[BK][BM];
    __shared__ __align__(16) float Ws[BK][BN];

    const int tid = threadIdx.x;
    const int blockRow = blockIdx.y * BM;
    const int blockCol = blockIdx.x * BN;

    const int arow = tid >> 1;
    const int acol = (tid & 1) * 4;
    const int wrow = tid >> 5;
    const int wcol = (tid & 31) * 4;

    const int tm = (tid >> 4) * TM;
    const int tn = (tid & 15) * TN;

    float acc[TM][TN];
#pragma unroll
    for (int i = 0; i < TM; i++)
#pragma unroll
        for (int j = 0; j < TN; j++) acc[i][j] = 0.0f;

    for (int k0 = 0; k0 < K; k0 += BK) {
        {
            const int gr = blockRow + arow;
            float4 v = make_float4(0.f, 0.f, 0.f, 0.f);
            if (gr < M)
                v = *reinterpret_cast<const float4*>(A + (size_t)gr * lda + k0 + acol);
            As[acol + 0][arow] = v.x;
            As[acol + 1][arow] = v.y;
            As[acol + 2][arow] = v.z;
            As[acol + 3][arow] = v.w;
        }
        {
            const int gk = k0 + wrow;
            const int gn = blockCol + wcol;
            float4 v = make_float4(0.f, 0.f, 0.f, 0.f);
            if (gn < N)
                v = *reinterpret_cast<const float4*>(W + (size_t)gk * ldw + gn);
            Ws[wrow][wcol + 0] = v.x;
            Ws[wrow][wcol + 1] = v.y;
            Ws[wrow][wcol + 2] = v.z;
            Ws[wrow][wcol + 3] = v.w;
        }
        __syncthreads();

#pragma unroll
        for (int k = 0; k < BK; k++) {
            float ra[TM], rb[TN];
            *reinterpret_cast<float4*>(&ra[0]) = *reinterpret_cast<const float4*>(&As[k][tm]);
            *reinterpret_cast<float4*>(&ra[4]) = *reinterpret_cast<const float4*>(&As[k][tm + 4]);
            *reinterpret_cast<float4*>(&rb[0]) = *reinterpret_cast<const float4*>(&Ws[k][tn]);
            *reinterpret_cast<float4*>(&rb[4]) = *reinterpret_cast<const float4*>(&Ws[k][tn + 4]);
#pragma unroll
            for (int i = 0; i < TM; i++)
#pragma unroll
                for (int j = 0; j < TN; j++)
                    acc[i][j] = fmaf(ra[i], rb[j], acc[i][j]);
        }
        __syncthreads();
    }

#pragma unroll
    for (int i = 0; i < TM; i++) {
        const int gm = blockRow + tm + i;
        if (gm >= M) continue;
#pragma unroll
        for (int j = 0; j < TN; j++) {
            const int gn = blockCol + tn + j;
            if (gn >= N) continue;
            float v = acc[i][j] + bias[gn];
            if (relu) v = fmaxf(v, 0.0f);
            C[(size_t)gm * ldc + gn] = v;
        }
    }
}

// ---------------------------------------------------------------------------
__global__ void seg_mean_kernel(const float* __restrict__ h,
                                const int* __restrict__ idx,
                                float* __restrict__ hm, int group)
{
    const int b = blockIdx.x;
    const int c = threadIdx.x;
    const float* base = h + (size_t)b * group * 256 + c;
    float s = 0.0f;
    for (int i = 0; i < group; i++) s += base[(size_t)i * 256];
    hm[(size_t)b * 256 + c] = s / (float)idx[b];
}

__global__ void final_kernel(const float* __restrict__ w,
                             const float* __restrict__ f3w,
                             const float* __restrict__ f3b,
                             float* __restrict__ out, int B)
{
    const int r = blockIdx.x * blockDim.x + threadIdx.x;
    if (r >= B) return;
    float s = 0.0f;
#pragma unroll
    for (int k = 0; k < 32; k++) s = fmaf(w[(size_t)r * 32 + k], f3w[k], s);
    out[r] = s + f3b[0];
}

// ---------------------------------------------------------------------------
static inline dim3 simt_grid(int M, int N) {
    return dim3((N + BN - 1) / BN, (M + BM - 1) / BM);
}

extern "C" void kernel_launch(void* const* d_in, const int* in_sizes, int n_in,
                              void* d_out, int out_size)
{
    const float* pairs     = (const float*)d_in[0];
    const int*   idx_pairs = (const int*)  d_in[1];
    const float* aw  = (const float*)d_in[3];
    const float* ab  = (const float*)d_in[4];
    const float* bw  = (const float*)d_in[5];
    const float* bb  = (const float*)d_in[6];
    const float* p1w = (const float*)d_in[7];
    const float* p1b = (const float*)d_in[8];
    const float* p2w = (const float*)d_in[9];
    const float* p2b = (const float*)d_in[10];
    const float* p3w = (const float*)d_in[11];
    const float* p3b = (const float*)d_in[12];
    const float* f1w = (const float*)d_in[13];
    const float* f1b = (const float*)d_in[14];
    const float* f2w = (const float*)d_in[15];
    const float* f2b = (const float*)d_in[16];
    const float* f3w = (const float*)d_in[17];
    const float* f3b = (const float*)d_in[18];
    float* out = (float*)d_out;

    const int P = in_sizes[0] / 160;
    const int B = in_sizes[1];
    const int group = P / B;

    float *h384, *h512, *h256, *hm, *y, *z, *w, *wt;
    cudaGetSymbolAddress((void**)&h384, g_h384);
    cudaGetSymbolAddress((void**)&h512, g_h512);
    cudaGetSymbolAddress((void**)&h256, g_h256);
    cudaGetSymbolAddress((void**)&hm,   g_hm);
    cudaGetSymbolAddress((void**)&y,    g_y);
    cudaGetSymbolAddress((void**)&z,    g_z);
    cudaGetSymbolAddress((void**)&w,    g_w);
    cudaGetSymbolAddress((void**)&wt,   g_wt);

    float* awr = wt;                      // [64][128]
    float* bwr = awr + 64 * 128;          // [32][128]
    float* p1r = bwr + 32 * 128;          // [384][512]
    float* p2r = p1r + 384 * 512;         // [512][256]

    round_copy<<<(64 * 128 / 4 + 255) / 256, 256>>>(aw, awr, 64 * 128 / 4);
    round_copy<<<(32 * 128 / 4 + 255) / 256, 256>>>(bw, bwr, 32 * 128 / 4);
    round_copy<<<(384 * 512 / 4 + 255) / 256, 256>>>(p1w, p1r, 384 * 512 / 4);
    round_copy<<<(512 * 256 / 4 + 255) / 256, 256>>>(p2w, p2r, 512 * 256 / 4);

    const int MT = (P + 127) / 128;

    // embed: three column slabs of h384 (cvt_a rounds raw pairs on the fly)
    tc_gemm<<<dim3(MT, 1), 256>>>(pairs,       160, awr, ab, h384,       384, P, 128, 64, 1, 1, 1);
    tc_gemm<<<dim3(MT, 1), 256>>>(pairs + 64,  160, awr, ab, h384 + 128, 384, P, 128, 64, 1, 1, 1);
    tc_gemm<<<dim3(MT, 1), 256>>>(pairs + 128, 160, bwr, bb, h384 + 256, 384, P, 128, 32, 1, 1, 1);

    // trunk
    tc_gemm<<<dim3(MT, 4), 256>>>(h384, 384, p1r, p1b, h512, 512, P, 512, 384, 1, 1, 0);
    tc_gemm<<<dim3(MT, 2), 256>>>(h512, 512, p2r, p2b, h256, 256, P, 256, 512, 1, 0, 0);

    // segment mean before p3 (p3 linear)
    seg_mean_kernel<<<B, 256>>>(h256, idx_pairs, hm, group);

    // batch-level fp32 SIMT
    gemm_bias_act<<<simt_grid(B, 1024), 256>>>(hm, 256, p3w, 1024, p3b, y, 1024, B, 1024, 256, 0);
    gemm_bias_act<<<simt_grid(B, 512),  256>>>(y, 1024, f1w, 512,  f1b, z, 512,  B, 512, 1024, 1);
    gemm_bias_act<<<simt_grid(B, 32),   256>>>(z, 512,  f2w, 32,   f2b, w, 32,   B, 32,  512,  1);
    final_kernel<<<(B + 255) / 256, 256>>>(w, f3w, f3b, out, B);
}

// round 4
// speedup vs baseline: 4.5587x; 1.5967x over previous
#include <cuda_runtime.h>
#include <cuda_bf16.h>
#include <cstdint>

// ===========================================================================
// TGNN — bf16 mma.sync trunk + tf32 batch layers.
//   trunk (P=200k rows): embed(x3) -> p1 -> p2, all bf16 m16n8k16 tensor GEMM
//   segment-mean (fp32 accum) BEFORE p3 (linear)
//   batch (B=2000 rows): p3, f1 on tf32 m16n8k8; f2/final SIMT fp32
// ===========================================================================

#define P_MAX  200000
#define B_MAX  2000

__device__ __nv_bfloat16 g_pairs_bf[(size_t)P_MAX * 160];
__device__ __nv_bfloat16 g_h384[(size_t)P_MAX * 384];
__device__ __nv_bfloat16 g_h512[(size_t)P_MAX * 512];
__device__ __nv_bfloat16 g_h256[(size_t)P_MAX * 256];
__device__ float g_hm  [(size_t)B_MAX * 256];
__device__ float g_y   [(size_t)B_MAX * 1024];
__device__ float g_z   [(size_t)B_MAX * 512];
__device__ float g_w   [(size_t)B_MAX * 32];
__device__ __nv_bfloat16 g_wbf[1024 * 1024];   // bf16 transposed weights
__device__ float g_wtf [1024 * 1024];          // tf32-rounded weights (p3, f1)

// ---------------------------------------------------------------------------
__device__ __forceinline__ float tf32_round(float x) {
    uint32_t r;
    asm("cvt.rna.tf32.f32 %0, %1;" : "=r"(r) : "f"(x));
    return __uint_as_float(r);
}
__device__ __forceinline__ uint32_t tf32_round_bits(float x) {
    uint32_t r;
    asm("cvt.rna.tf32.f32 %0, %1;" : "=r"(r) : "f"(x));
    return r;
}
__device__ __forceinline__ void cp_async16(uint32_t smem_addr, const void* gptr, int src_bytes) {
    asm volatile("cp.async.ca.shared.global [%0], [%1], 16, %2;\n"
                 :: "r"(smem_addr), "l"(gptr), "r"(src_bytes));
}
#define CP_ASYNC_COMMIT() asm volatile("cp.async.commit_group;\n" ::: "memory")
#define CP_ASYNC_WAIT0()  asm volatile("cp.async.wait_group 0;\n" ::: "memory")

__device__ __forceinline__ uint32_t smem_u32(const void* p) {
    uint32_t a;
    asm("{ .reg .u64 t; cvta.to.shared.u64 t, %1; cvt.u32.u64 %0, t; }" : "=r"(a) : "l"(p));
    return a;
}
__device__ __forceinline__ void mma_bf16(float& c0, float& c1, float& c2, float& c3,
                                         uint32_t a0, uint32_t a1, uint32_t a2, uint32_t a3,
                                         uint32_t b0, uint32_t b1) {
    asm volatile(
        "mma.sync.aligned.m16n8k16.row.col.f32.bf16.bf16.f32 "
        "{%0,%1,%2,%3}, {%4,%5,%6,%7}, {%8,%9}, {%0,%1,%2,%3};"
        : "+f"(c0), "+f"(c1), "+f"(c2), "+f"(c3)
        : "r"(a0), "r"(a1), "r"(a2), "r"(a3), "r"(b0), "r"(b1));
}
__device__ __forceinline__ void mma_tf32(float& c0, float& c1, float& c2, float& c3,
                                         uint32_t a0, uint32_t a1, uint32_t a2, uint32_t a3,
                                         uint32_t b0, uint32_t b1) {
    asm volatile(
        "mma.sync.aligned.m16n8k8.row.col.f32.tf32.tf32.f32 "
        "{%0,%1,%2,%3}, {%4,%5,%6,%7}, {%8,%9}, {%0,%1,%2,%3};"
        : "+f"(c0), "+f"(c1), "+f"(c2), "+f"(c3)
        : "r"(a0), "r"(a1), "r"(a2), "r"(a3), "r"(b0), "r"(b1));
}

// ===========================================================================
// bf16 tensor GEMM: C[M,N] = act(A[M,K] @ WT[N,K]^T + bias)
//   BM=128, BN=128, BK=32, 256 threads (8 warps, 4x2), double-buffered.
//   A smem [m][k], row stride 40 bf16 (20 words): bank = (20g+t)%32 exact.
//   B smem [n][k], same stride: fragments are direct packed-pair LDS.32.
//   K % 32 == 0, N % 128 == 0, lda bytes % 16 == 0.
// ===========================================================================
#define BROW_W 20                        // words per smem row
#define BROW_B 80                        // bytes per smem row
#define TILE_SZ (128 * BROW_B)           // 10240 B per tile
#define STG_BF (2 * TILE_SZ)             // A + B per stage
#define SMEM_BF (2 * STG_BF)             // 40960 B

__global__ __launch_bounds__(256)
void tc_gemm_bf16(const __nv_bfloat16* __restrict__ A, int lda,
                  const __nv_bfloat16* __restrict__ WT,   // [N][K]
                  const float* __restrict__ bias,
                  void* __restrict__ Cv, int ldc,
                  int M, int N, int K, int relu, int out_bf16)
{
    __shared__ __align__(16) char smem[SMEM_BF];
    const uint32_t smem_base = smem_u32(smem);

    const int tid  = threadIdx.x;
    const int wid  = tid >> 5;
    const int lane = tid & 31;
    const int g    = lane >> 2;
    const int t    = lane & 3;

    const int blockRow = blockIdx.x * 128;
    const int blockCol = blockIdx.y * 128;
    const int warp_m = (wid & 3) * 32;
    const int warp_n = (wid >> 2) * 64;

    const int NIT = K >> 5;

    float acc[2][8][4];
#pragma unroll
    for (int mt = 0; mt < 2; mt++)
#pragma unroll
        for (int nt = 0; nt < 8; nt++)
#pragma unroll
            for (int i = 0; i < 4; i++) acc[mt][nt][i] = 0.0f;

    auto load_tiles = [&](int it, int stage) {
        const int k0 = it << 5;
        const uint32_t sa = smem_base + stage * STG_BF;
        const uint32_t sb = sa + TILE_SZ;
#pragma unroll
        for (int h = 0; h < 2; h++) {
            const int chunk = tid + h * 256;          // 0..511
            const int row = chunk >> 2;
            const int ck  = chunk & 3;
            const int gr = blockRow + row;
            const char* p = (const char*)(A + (size_t)gr * lda + k0 + ck * 8);
            cp_async16(sa + row * BROW_B + ck * 16, p, gr < M ? 16 : 0);
        }
#pragma unroll
        for (int h = 0; h < 2; h++) {
            const int chunk = tid + h * 256;
            const int n  = chunk >> 2;
            const int ck = chunk & 3;
            const char* p = (const char*)(WT + (size_t)(blockCol + n) * K + k0 + ck * 8);
            cp_async16(sb + n * BROW_B + ck * 16, p, 16);
        }
        CP_ASYNC_COMMIT();
    };

    load_tiles(0, 0);
    int fetch = 1;

    for (int it = 0; it < NIT; it++) {
        CP_ASYNC_WAIT0();
        __syncthreads();
        if (fetch < NIT) { load_tiles(fetch, fetch & 1); fetch++; }

        const uint32_t* Aw = (const uint32_t*)(smem + (it & 1) * STG_BF);
        const uint32_t* Bw = (const uint32_t*)(smem + (it & 1) * STG_BF + TILE_SZ);

#pragma unroll
        for (int ks = 0; ks < 2; ks++) {              // two k16 blocks
            const int kw = ks * 8 + t;
            uint32_t a[2][4];
#pragma unroll
            for (int mt = 0; mt < 2; mt++) {
                const int m0 = warp_m + mt * 16 + g;
                a[mt][0] = Aw[m0 * BROW_W + kw];
                a[mt][1] = Aw[(m0 + 8) * BROW_W + kw];
                a[mt][2] = Aw[m0 * BROW_W + kw + 4];
                a[mt][3] = Aw[(m0 + 8) * BROW_W + kw + 4];
            }
            uint32_t b[8][2];
#pragma unroll
            for (int nt = 0; nt < 8; nt++) {
                const int n0 = warp_n + nt * 8 + g;
                b[nt][0] = Bw[n0 * BROW_W + kw];
                b[nt][1] = Bw[n0 * BROW_W + kw + 4];
            }
#pragma unroll
            for (int mt = 0; mt < 2; mt++)
#pragma unroll
                for (int nt = 0; nt < 8; nt++)
                    mma_bf16(acc[mt][nt][0], acc[mt][nt][1], acc[mt][nt][2], acc[mt][nt][3],
                             a[mt][0], a[mt][1], a[mt][2], a[mt][3],
                             b[nt][0], b[nt][1]);
        }
        __syncthreads();
    }

    // ---- epilogue ----
#pragma unroll
    for (int nt = 0; nt < 8; nt++) {
        const int col = blockCol + warp_n + nt * 8 + 2 * t;
        const float2 bv = *reinterpret_cast<const float2*>(&bias[col]);
#pragma unroll
        for (int mt = 0; mt < 2; mt++) {
#pragma unroll
            for (int half = 0; half < 2; half++) {
                const int row = blockRow + warp_m + mt * 16 + g + half * 8;
                if (row >= M) continue;
                float v0 = acc[mt][nt][half * 2 + 0] + bv.x;
                float v1 = acc[mt][nt][half * 2 + 1] + bv.y;
                if (relu) { v0 = fmaxf(v0, 0.f); v1 = fmaxf(v1, 0.f); }
                if (out_bf16) {
                    __nv_bfloat162 pv = __float22bfloat162_rn(make_float2(v0, v1));
                    *reinterpret_cast<__nv_bfloat162*>(
                        (__nv_bfloat16*)Cv + (size_t)row * ldc + col) = pv;
                } else {
                    *reinterpret_cast<float2*>(
                        (float*)Cv + (size_t)row * ldc + col) = make_float2(v0, v1);
                }
            }
        }
    }
}

// ===========================================================================
// tf32 tensor GEMM (proven R3 kernel) — batch layers p3, f1
// ===========================================================================
#define ASTRIDE 20
#define BSTRIDE 136
#define ASZ (128 * ASTRIDE * 4)
#define BSZ (16 * BSTRIDE * 4)
#define STG (ASZ + BSZ)
#define SMEM_TF (2 * STG)

__global__ __launch_bounds__(256)
void tc_gemm_tf32(const float* __restrict__ A, int lda,
                  const float* __restrict__ W,        // [K][N], pre-rounded
                  const float* __restrict__ bias,
                  float* __restrict__ C, int ldc,
                  int M, int N, int K, int relu)
{
    __shared__ __align__(16) char smem[SMEM_TF];
    const uint32_t smem_base = smem_u32(smem);

    const int tid  = threadIdx.x;
    const int wid  = tid >> 5;
    const int lane = tid & 31;
    const int g    = lane >> 2;
    const int t    = lane & 3;

    const int blockRow = blockIdx.x * 128;
    const int blockCol = blockIdx.y * 128;
    const int warp_m = (wid & 3) * 32;
    const int warp_n = (wid >> 2) * 64;

    const int am0 = tid >> 2;
    const int akc = tid & 3;
    const int bk0 = tid >> 5;
    const int bnc = tid & 31;

    const int NIT = K >> 4;

    float acc[2][8][4];
#pragma unroll
    for (int mt = 0; mt < 2; mt++)
#pragma unroll
        for (int nt = 0; nt < 8; nt++)
#pragma unroll
            for (int i = 0; i < 4; i++) acc[mt][nt][i] = 0.0f;

    auto load_tiles = [&](int it, int stage) {
        const int k0 = it << 4;
        const uint32_t sa = smem_base + stage * STG;
        const uint32_t sb = sa + ASZ;
        {
            int r0 = blockRow + am0;
            int r1 = r0 + 64;
            const char* p0 = (const char*)(A + (size_t)r0 * lda + k0 + akc * 4);
            const char* p1 = (const char*)(A + (size_t)r1 * lda + k0 + akc * 4);
            cp_async16(sa + am0 * (ASTRIDE * 4) + akc * 16, p0, r0 < M ? 16 : 0);
            cp_async16(sa + (am0 + 64) * (ASTRIDE * 4) + akc * 16, p1, r1 < M ? 16 : 0);
        }
        {
            const char* p0 = (const char*)(W + (size_t)(k0 + bk0) * N + blockCol + bnc * 4);
            const char* p1 = (const char*)(W + (size_t)(k0 + bk0 + 8) * N + blockCol + bnc * 4);
            cp_async16(sb + bk0 * (BSTRIDE * 4) + bnc * 16, p0, 16);
            cp_async16(sb + (bk0 + 8) * (BSTRIDE * 4) + bnc * 16, p1, 16);
        }
        CP_ASYNC_COMMIT();
    };

    load_tiles(0, 0);
    int fetch = 1;

    for (int it = 0; it < NIT; it++) {
        CP_ASYNC_WAIT0();
        __syncthreads();
        if (fetch < NIT) { load_tiles(fetch, fetch & 1); fetch++; }

        const float* As = (const float*)(smem + (it & 1) * STG);
        const float* Bs = (const float*)(smem + (it & 1) * STG + ASZ);

#pragma unroll
        for (int ks = 0; ks < 2; ks++) {
            uint32_t a[2][4];
#pragma unroll
            for (int mt = 0; mt < 2; mt++) {
                const int m0 = warp_m + mt * 16 + g;
                const int kk = ks * 8 + t;
                a[mt][0] = tf32_round_bits(As[m0 * ASTRIDE + kk]);
                a[mt][1] = tf32_round_bits(As[(m0 + 8) * ASTRIDE + kk]);
                a[mt][2] = tf32_round_bits(As[m0 * ASTRIDE + kk + 4]);
                a[mt][3] = tf32_round_bits(As[(m0 + 8) * ASTRIDE + kk + 4]);
            }
            uint32_t b[8][2];
#pragma unroll
            for (int nt = 0; nt < 8; nt++) {
                const int n0 = warp_n + nt * 8 + g;
                const int kk = ks * 8 + t;
                b[nt][0] = __float_as_uint(Bs[kk * BSTRIDE + n0]);
                b[nt][1] = __float_as_uint(Bs[(kk + 4) * BSTRIDE + n0]);
            }
#pragma unroll
            for (int mt = 0; mt < 2; mt++)
#pragma unroll
                for (int nt = 0; nt < 8; nt++)
                    mma_tf32(acc[mt][nt][0], acc[mt][nt][1], acc[mt][nt][2], acc[mt][nt][3],
                             a[mt][0], a[mt][1], a[mt][2], a[mt][3],
                             b[nt][0], b[nt][1]);
        }
        __syncthreads();
    }

#pragma unroll
    for (int nt = 0; nt < 8; nt++) {
        const int col = blockCol + warp_n + nt * 8 + 2 * t;
        const float2 bv = *reinterpret_cast<const float2*>(&bias[col]);
#pragma unroll
        for (int mt = 0; mt < 2; mt++) {
#pragma unroll
            for (int half = 0; half < 2; half++) {
                const int row = blockRow + warp_m + mt * 16 + g + half * 8;
                if (row >= M) continue;
                float v0 = acc[mt][nt][half * 2 + 0] + bv.x;
                float v1 = acc[mt][nt][half * 2 + 1] + bv.y;
                if (relu) { v0 = fmaxf(v0, 0.f); v1 = fmaxf(v1, 0.f); }
                *reinterpret_cast<float2*>(C + (size_t)row * ldc + col) = make_float2(v0, v1);
            }
        }
    }
}

// ---------------------------------------------------------------------------
// conversions
// ---------------------------------------------------------------------------
__global__ void cvt_f32_bf16(const float* __restrict__ src,
                             __nv_bfloat16* __restrict__ dst, int n2)
{
    int i = blockIdx.x * blockDim.x + threadIdx.x;
    if (i >= n2) return;
    float2 v = reinterpret_cast<const float2*>(src)[i];
    reinterpret_cast<__nv_bfloat162*>(dst)[i] = __float22bfloat162_rn(v);
}

// out[n*K + k] = bf16(in[k*N + n])
__global__ void wt_bf16(const float* __restrict__ in,
                        __nv_bfloat16* __restrict__ out, int K, int N)
{
    int i = blockIdx.x * blockDim.x + threadIdx.x;
    if (i >= K * N) return;
    int n = i / K, k = i % K;
    out[i] = __float2bfloat16(in[(size_t)k * N + n]);
}

__global__ void round_copy(const float* __restrict__ src, float* __restrict__ dst, int n4)
{
    int i = blockIdx.x * blockDim.x + threadIdx.x;
    if (i >= n4) return;
    float4 v = reinterpret_cast<const float4*>(src)[i];
    v.x = tf32_round(v.x); v.y = tf32_round(v.y);
    v.z = tf32_round(v.z); v.w = tf32_round(v.w);
    reinterpret_cast<float4*>(dst)[i] = v;
}

// ---------------------------------------------------------------------------
// segment mean: bf16 in, fp32 accum, fp32 out
// ---------------------------------------------------------------------------
__global__ void seg_mean_kernel(const __nv_bfloat16* __restrict__ h,
                                const int* __restrict__ idx,
                                float* __restrict__ hm, int group)
{
    const int b = blockIdx.x;
    const int c = threadIdx.x;
    const __nv_bfloat16* base = h + (size_t)b * group * 256 + c;
    float s = 0.0f;
    for (int i = 0; i < group; i++) s += __bfloat162float(base[(size_t)i * 256]);
    hm[(size_t)b * 256 + c] = s / (float)idx[b];
}

// ---------------------------------------------------------------------------
// small SIMT layers
// ---------------------------------------------------------------------------
__global__ __launch_bounds__(256, 2)
void gemm_simt(const float* __restrict__ A, int lda,
               const float* __restrict__ W, int ldw,
               const float* __restrict__ bias,
               float* __restrict__ C, int ldc,
               int M, int N, int K, int relu)
{
    int gm = blockIdx.x * 64 + (threadIdx.x >> 2);
    int nq = (threadIdx.x & 3) * 8;
    if (gm >= M) return;
    float acc[8] = {0,0,0,0,0,0,0,0};
    const float* a = A + (size_t)gm * lda;
    for (int k = 0; k < K; k++) {
        float av = a[k];
        const float* wr = W + (size_t)k * ldw + nq;
#pragma unroll
        for (int j = 0; j < 8; j++) acc[j] = fmaf(av, wr[j], acc[j]);
    }
#pragma unroll
    for (int j = 0; j < 8; j++) {
        float v = acc[j] + bias[nq + j];
        if (relu) v = fmaxf(v, 0.0f);
        C[(size_t)gm * ldc + nq + j] = v;
    }
}

__global__ void final_kernel(const float* __restrict__ w,
                             const float* __restrict__ f3w,
                             const float* __restrict__ f3b,
                             float* __restrict__ out, int B)
{
    const int r = blockIdx.x * blockDim.x + threadIdx.x;
    if (r >= B) return;
    float s = 0.0f;
#pragma unroll
    for (int k = 0; k < 32; k++) s = fmaf(w[(size_t)r * 32 + k], f3w[k], s);
    out[r] = s + f3b[0];
}

// ---------------------------------------------------------------------------
extern "C" void kernel_launch(void* const* d_in, const int* in_sizes, int n_in,
                              void* d_out, int out_size)
{
    const float* pairs     = (const float*)d_in[0];
    const int*   idx_pairs = (const int*)  d_in[1];
    const float* aw  = (const float*)d_in[3];
    const float* ab  = (const float*)d_in[4];
    const float* bw  = (const float*)d_in[5];
    const float* bb  = (const float*)d_in[6];
    const float* p1w = (const float*)d_in[7];
    const float* p1b = (const float*)d_in[8];
    const float* p2w = (const float*)d_in[9];
    const float* p2b = (const float*)d_in[10];
    const float* p3w = (const float*)d_in[11];
    const float* p3b = (const float*)d_in[12];
    const float* f1w = (const float*)d_in[13];
    const float* f1b = (const float*)d_in[14];
    const float* f2w = (const float*)d_in[15];
    const float* f2b = (const float*)d_in[16];
    const float* f3w = (const float*)d_in[17];
    const float* f3b = (const float*)d_in[18];
    float* out = (float*)d_out;

    const int P = in_sizes[0] / 160;
    const int B = in_sizes[1];
    const int group = P / B;

    __nv_bfloat16 *pairs_bf, *h384, *h512, *h256, *wbf;
    float *hm, *y, *z, *w, *wtf;
    cudaGetSymbolAddress((void**)&pairs_bf, g_pairs_bf);
    cudaGetSymbolAddress((void**)&h384, g_h384);
    cudaGetSymbolAddress((void**)&h512, g_h512);
    cudaGetSymbolAddress((void**)&h256, g_h256);
    cudaGetSymbolAddress((void**)&hm,   g_hm);
    cudaGetSymbolAddress((void**)&y,    g_y);
    cudaGetSymbolAddress((void**)&z,    g_z);
    cudaGetSymbolAddress((void**)&w,    g_w);
    cudaGetSymbolAddress((void**)&wbf,  g_wbf);
    cudaGetSymbolAddress((void**)&wtf,  g_wtf);

    // bf16 transposed weights [N][K]
    __nv_bfloat16* awt = wbf;                    // [128][64]
    __nv_bfloat16* bwt = awt + 128 * 64;         // [128][32]
    __nv_bfloat16* p1t = bwt + 128 * 32;         // [512][384]
    __nv_bfloat16* p2t = p1t + 512 * 384;        // [256][512]
    // tf32 weights [K][N]
    float* p3r = wtf;                            // [256][1024]
    float* f1r = p3r + 256 * 1024;               // [1024][512]

    wt_bf16<<<(128 * 64  + 255) / 256, 256>>>(aw,  awt, 64, 128);
    wt_bf16<<<(128 * 32  + 255) / 256, 256>>>(bw,  bwt, 32, 128);
    wt_bf16<<<(512 * 384 + 255) / 256, 256>>>(p1w, p1t, 384, 512);
    wt_bf16<<<(256 * 512 + 255) / 256, 256>>>(p2w, p2t, 512, 256);
    round_copy<<<(256 * 1024 / 4 + 255) / 256, 256>>>(p3w, p3r, 256 * 1024 / 4);
    round_copy<<<(1024 * 512 / 4 + 255) / 256, 256>>>(f1w, f1r, 1024 * 512 / 4);

    cvt_f32_bf16<<<((P * 160 / 2) + 255) / 256, 256>>>(pairs, pairs_bf, P * 160 / 2);

    const int MT = (P + 127) / 128;

    // embed: three column slabs of h384
    tc_gemm_bf16<<<dim3(MT, 1), 256>>>(pairs_bf,       160, awt, ab, h384,       384, P, 128, 64, 1, 1);
    tc_gemm_bf16<<<dim3(MT, 1), 256>>>(pairs_bf + 64,  160, awt, ab, h384 + 128, 384, P, 128, 64, 1, 1);
    tc_gemm_bf16<<<dim3(MT, 1), 256>>>(pairs_bf + 128, 160, bwt, bb, h384 + 256, 384, P, 128, 32, 1, 1);

    // trunk
    tc_gemm_bf16<<<dim3(MT, 4), 256>>>(h384, 384, p1t, p1b, h512, 512, P, 512, 384, 1, 1);
    tc_gemm_bf16<<<dim3(MT, 2), 256>>>(h512, 512, p2t, p2b, h256, 256, P, 256, 512, 1, 1);

    // segment mean before p3 (p3 linear)
    seg_mean_kernel<<<B, 256>>>(h256, idx_pairs, hm, group);

    // batch-level: tf32 tensor for p3/f1, SIMT for f2/final
    const int BT = (B + 127) / 128;
    tc_gemm_tf32<<<dim3(BT, 8), 256>>>(hm, 256, p3r, p3b, y, 1024, B, 1024, 256, 0);
    tc_gemm_tf32<<<dim3(BT, 4), 256>>>(y, 1024, f1r, f1b, z, 512,  B, 512, 1024, 1);
    gemm_simt<<<(B + 63) / 64, 256>>>(z, 512, f2w, 32, f2b, w, 32, B, 32, 512, 1);
    final_kernel<<<(B + 255) / 256, 256>>>(w, f3w, f3b, out, B);
}